// round 1
// baseline (speedup 1.0000x reference)
#include <cuda_runtime.h>
#include <cuda_bf16.h>
#include <cub/cub.cuh>
#include <cfloat>
#include <cstdint>

// ---------------------------------------------------------------------------
// RetinaNet postprocess: decode + score-max + threshold + greedy NMS(300) + gather
//
// Equivalence argument vs reference argmax-loop NMS:
//   argmax-loop == stable sort by (score desc, idx asc) then greedy scan
//   keeping each candidate not suppressed (IoU > 0.5) by any earlier keep.
//   CUB radix sort is stable => equal scores keep ascending-index order,
//   matching jnp.argmax first-max semantics exactly.
// ---------------------------------------------------------------------------

#define MAXA   262144
#define MAXDET 300
#define PSTTHD 0.05f
#define NMSTHD 0.5f

__device__ float  g_keys_in [MAXA];
__device__ int    g_vals_in [MAXA];
__device__ float  g_keys_out[MAXA];
__device__ int    g_vals_out[MAXA];
__device__ float4 g_boxes   [MAXA];
__device__ float  g_areas   [MAXA];
__device__ int    g_keep    [MAXDET];
__device__ int    g_nkept;
__device__ unsigned char g_sort_temp[32u << 20];  // 32 MB CUB temp storage

// ---------------------------------------------------------------------------
// Kernel 1: per-anchor class-max score, box decode+clip, sort-key emit
// ---------------------------------------------------------------------------
__global__ void prep_kernel(const float* __restrict__ cls,
                            const float* __restrict__ reg,
                            const float* __restrict__ anc,
                            const int*   __restrict__ ph,
                            const int*   __restrict__ pw,
                            int A, int C)
{
    int a = blockIdx.x * blockDim.x + threadIdx.x;
    if (a >= A) return;

    // max over C classes (C=80 => 20 float4 loads, 320B/thread streaming)
    const float* row = cls + (size_t)a * C;
    float m = -FLT_MAX;
    if ((C & 3) == 0) {
        const float4* r4 = (const float4*)row;
        int n4 = C >> 2;
        #pragma unroll 4
        for (int i = 0; i < n4; i++) {
            float4 v = r4[i];
            m = fmaxf(m, fmaxf(fmaxf(v.x, v.y), fmaxf(v.z, v.w)));
        }
    } else {
        for (int i = 0; i < C; i++) m = fmaxf(m, row[i]);
    }

    // decode
    float4 an = ((const float4*)anc)[a];
    float4 rg = ((const float4*)reg)[a];
    float w  = an.z - an.x;
    float h  = an.w - an.y;
    float cx = an.x + 0.5f * w;
    float cy = an.y + 0.5f * h;
    float dx = rg.x * 0.1f, dy = rg.y * 0.1f;
    float dw = rg.z * 0.2f, dh = rg.w * 0.2f;
    float pcx = cx + dx * w;
    float pcy = cy + dy * h;
    float pw_ = expf(dw) * w;
    float ph_ = expf(dh) * h;

    float W = pw ? (float)__ldg(pw) : 1024.0f;
    float H = ph ? (float)__ldg(ph) : 1024.0f;

    float x1 = fmaxf(pcx - 0.5f * pw_, 0.0f);
    float y1 = fmaxf(pcy - 0.5f * ph_, 0.0f);
    float x2 = fminf(pcx + 0.5f * pw_, W);
    float y2 = fminf(pcy + 0.5f * ph_, H);

    g_boxes[a] = make_float4(x1, y1, x2, y2);
    g_areas[a] = (x2 - x1) * (y2 - y1);
    g_keys_in[a] = (m > PSTTHD) ? m : -FLT_MAX;  // -FLT_MAX sorts last (desc)
    g_vals_in[a] = a;
}

// ---------------------------------------------------------------------------
// Kernel 2: single-block greedy NMS over the sorted candidate list.
// Kept set lives in SMEM (<=300). Batch of 128 candidates tested in parallel
// against kept-set-at-batch-start; thread 0 serializes intra-batch acceptance.
// ---------------------------------------------------------------------------
__global__ void nms_kernel(int A)
{
    const int B = 128;
    __shared__ float kx1[MAXDET], ky1[MAXDET], kx2[MAXDET], ky2[MAXDET], kar[MAXDET];
    __shared__ float cx1[B], cy1[B], cx2[B], cy2[B], car[B];
    __shared__ int   cidx[B];
    __shared__ unsigned char cval[B], csup[B];
    __shared__ int n_kept, stop;

    int t = threadIdx.x;
    if (t == 0) { n_kept = 0; stop = 0; }
    __syncthreads();

    for (int pos = 0; pos < A; pos += B) {
        if (n_kept >= MAXDET || stop) break;

        int i = pos + t;
        bool v = false, sup = false;
        float x1 = 0.f, y1 = 0.f, x2 = 0.f, y2 = 0.f, ar = 0.f;
        int idx = -1;
        if (i < A) {
            float key = g_keys_out[i];
            if (key > PSTTHD) {
                v = true;
                idx = g_vals_out[i];
                float4 b = g_boxes[idx];
                x1 = b.x; y1 = b.y; x2 = b.z; y2 = b.w;
                ar = g_areas[idx];
            }
        }
        int base = n_kept;   // all threads read before t0 mutates (post-sync)
        if (v) {
            for (int k = 0; k < base; k++) {
                float xx1 = fmaxf(x1, kx1[k]);
                float yy1 = fmaxf(y1, ky1[k]);
                float xx2 = fminf(x2, kx2[k]);
                float yy2 = fminf(y2, ky2[k]);
                float inter = fmaxf(xx2 - xx1, 0.f) * fmaxf(yy2 - yy1, 0.f);
                float iou = inter / (ar + kar[k] - inter + 1e-8f);
                if (iou > NMSTHD) { sup = true; break; }
            }
        }
        cval[t] = v; csup[t] = sup; cidx[t] = idx;
        cx1[t] = x1; cy1[t] = y1; cx2[t] = x2; cy2[t] = y2; car[t] = ar;
        __syncthreads();

        if (t == 0) {
            for (int b = 0; b < B; b++) {
                if (!cval[b]) { stop = 1; break; }   // sorted: no later valid cand
                if (csup[b]) continue;
                bool s = false;
                for (int k = base; k < n_kept; k++) {  // vs intra-batch accepts
                    float xx1 = fmaxf(cx1[b], kx1[k]);
                    float yy1 = fmaxf(cy1[b], ky1[k]);
                    float xx2 = fminf(cx2[b], kx2[k]);
                    float yy2 = fminf(cy2[b], ky2[k]);
                    float inter = fmaxf(xx2 - xx1, 0.f) * fmaxf(yy2 - yy1, 0.f);
                    float iou = inter / (car[b] + kar[k] - inter + 1e-8f);
                    if (iou > NMSTHD) { s = true; break; }
                }
                if (!s) {
                    kx1[n_kept] = cx1[b]; ky1[n_kept] = cy1[b];
                    kx2[n_kept] = cx2[b]; ky2[n_kept] = cy2[b];
                    kar[n_kept] = car[b];
                    g_keep[n_kept] = cidx[b];
                    n_kept++;
                    if (n_kept >= MAXDET) break;
                }
            }
        }
        __syncthreads();
    }
    if (t == 0) g_nkept = n_kept;
}

// ---------------------------------------------------------------------------
// Kernel 3: finalize — per kept detection, argmax over its class row (first-max
// semantics) via one warp each; write tuple-flattened output.
// Layout: scores[300] | class[300] | boxes[300*4] | valid[300]  (floats)
// ---------------------------------------------------------------------------
__global__ void final_kernel(const float* __restrict__ cls, int C,
                             float* __restrict__ out)
{
    int warp = (blockIdx.x * blockDim.x + threadIdx.x) >> 5;
    int lane = threadIdx.x & 31;
    if (warp >= MAXDET) return;

    int nk = g_nkept;
    bool valid = warp < nk;
    float score = 0.f, clsid = -1.f;
    float bx0 = 0.f, bx1 = 0.f, bx2 = 0.f, bx3 = 0.f;

    if (valid) {
        int idx = g_keep[warp];
        const float* row = cls + (size_t)idx * C;
        float best = -FLT_MAX;
        int bi = 0x7fffffff;
        for (int c = lane; c < C; c += 32) {
            float vv = row[c];
            if (vv > best) { best = vv; bi = c; }
        }
        #pragma unroll
        for (int off = 16; off; off >>= 1) {
            float ov = __shfl_down_sync(0xffffffffu, best, off);
            int   oi = __shfl_down_sync(0xffffffffu, bi,   off);
            if (ov > best || (ov == best && oi < bi)) { best = ov; bi = oi; }
        }
        best = __shfl_sync(0xffffffffu, best, 0);
        bi   = __shfl_sync(0xffffffffu, bi,   0);
        score = best;
        clsid = (float)bi;
        float4 b = g_boxes[idx];
        bx0 = b.x; bx1 = b.y; bx2 = b.z; bx3 = b.w;
    }
    if (lane == 0) {
        out[warp]              = score;
        out[MAXDET + warp]     = clsid;
        out[2 * MAXDET + 4 * warp + 0] = bx0;
        out[2 * MAXDET + 4 * warp + 1] = bx1;
        out[2 * MAXDET + 4 * warp + 2] = bx2;
        out[2 * MAXDET + 4 * warp + 3] = bx3;
        out[6 * MAXDET + warp] = valid ? 1.0f : 0.0f;
    }
}

// ---------------------------------------------------------------------------
extern "C" void kernel_launch(void* const* d_in, const int* in_sizes, int n_in,
                              void* d_out, int out_size)
{
    const float* cls = (const float*)d_in[0];
    const float* reg = (const float*)d_in[1];
    const float* anc = (const float*)d_in[2];
    const int*   ph  = (n_in > 3) ? (const int*)d_in[3] : nullptr;
    const int*   pw  = (n_in > 4) ? (const int*)d_in[4] : nullptr;

    int A = in_sizes[2] / 4;
    if (A > MAXA) A = MAXA;
    int C = in_sizes[0] / A;

    prep_kernel<<<(A + 255) / 256, 256>>>(cls, reg, anc, ph, pw, A, C);

    // stable descending radix sort on (score key, anchor idx)
    void *keys_in, *vals_in, *keys_out, *vals_out, *temp;
    cudaGetSymbolAddress(&keys_in,  g_keys_in);
    cudaGetSymbolAddress(&vals_in,  g_vals_in);
    cudaGetSymbolAddress(&keys_out, g_keys_out);
    cudaGetSymbolAddress(&vals_out, g_vals_out);
    cudaGetSymbolAddress(&temp,     g_sort_temp);

    size_t temp_bytes = 0;
    cub::DeviceRadixSort::SortPairsDescending(
        (void*)nullptr, temp_bytes,
        (const float*)keys_in, (float*)keys_out,
        (const int*)vals_in,   (int*)vals_out, A, 0, 32, (cudaStream_t)0);
    if (temp_bytes > sizeof(g_sort_temp)) temp_bytes = sizeof(g_sort_temp);
    cub::DeviceRadixSort::SortPairsDescending(
        temp, temp_bytes,
        (const float*)keys_in, (float*)keys_out,
        (const int*)vals_in,   (int*)vals_out, A, 0, 32, (cudaStream_t)0);

    nms_kernel<<<1, 128>>>(A);

    final_kernel<<<(MAXDET * 32 + 127) / 128, 128>>>(cls, C, (float*)d_out);
}

// round 2
// speedup vs baseline: 10.7094x; 10.7094x over previous
#include <cuda_runtime.h>
#include <cuda_bf16.h>
#include <cub/cub.cuh>
#include <cfloat>
#include <cstdint>

// ---------------------------------------------------------------------------
// RetinaNet postprocess, round 2.
// Pipeline: prep (decode+score-max) -> CUB stable desc sort -> exact NMS split:
//   pair_kernel : full-grid pairwise suppression bitmask for top T0 sorted
//   scan0       : 1-warp exact greedy over top T0 via bitmask
//   flagA       : full-grid suppressed-vs-kept-snapshot flags for tail
//   tailB       : 1-warp ordered walk of survivors vs post-snapshot keeps
// Exactness: greedy NMS == stable-sort + prefix scan; kept set monotone, so
// any candidate suppressed by a snapshot kept-set is suppressed at its turn.
// ---------------------------------------------------------------------------

#define MAXA   262144
#define MAXDET 300
#define T0     2048
#define W0     (T0 / 64)     // 64-bit words per mask row
#define PSTTHD 0.05f
#define NMSTHD 0.5f

__device__ float  g_keys_in [MAXA];
__device__ int    g_vals_in [MAXA];
__device__ float  g_keys_out[MAXA];
__device__ int    g_vals_out[MAXA];
__device__ float4 g_boxes   [MAXA];
__device__ float  g_areas   [MAXA];
__device__ unsigned long long g_mask[T0 * W0];        // 512 KB pairwise masks
__device__ unsigned int       g_surv[(MAXA - T0) / 32 + 32];
__device__ float4 g_kbox [MAXDET];
__device__ float  g_karea[MAXDET];
__device__ int    g_keep [MAXDET];
__device__ int    g_nk;
__device__ unsigned char g_sort_temp[32u << 20];

// Exact same arithmetic at every site (matches reference semantics).
__device__ __forceinline__ bool sup_test(float x1, float y1, float x2, float y2, float ar,
                                         float X1, float Y1, float X2, float Y2, float AR)
{
    float xx1 = fmaxf(x1, X1);
    float yy1 = fmaxf(y1, Y1);
    float xx2 = fminf(x2, X2);
    float yy2 = fminf(y2, Y2);
    float inter = fmaxf(xx2 - xx1, 0.0f) * fmaxf(yy2 - yy1, 0.0f);
    float iou = inter / (ar + AR - inter + 1e-8f);
    return iou > NMSTHD;
}

// ---------------------------------------------------------------------------
__global__ void prep_kernel(const float* __restrict__ cls,
                            const float* __restrict__ reg,
                            const float* __restrict__ anc,
                            const int*   __restrict__ ph,
                            const int*   __restrict__ pw,
                            int A, int C)
{
    int a = blockIdx.x * blockDim.x + threadIdx.x;
    if (a >= A) return;

    const float* row = cls + (size_t)a * C;
    float m = -FLT_MAX;
    if ((C & 3) == 0) {
        const float4* r4 = (const float4*)row;
        int n4 = C >> 2;
        #pragma unroll 4
        for (int i = 0; i < n4; i++) {
            float4 v = r4[i];
            m = fmaxf(m, fmaxf(fmaxf(v.x, v.y), fmaxf(v.z, v.w)));
        }
    } else {
        for (int i = 0; i < C; i++) m = fmaxf(m, row[i]);
    }

    float4 an = ((const float4*)anc)[a];
    float4 rg = ((const float4*)reg)[a];
    float w  = an.z - an.x;
    float h  = an.w - an.y;
    float cx = an.x + 0.5f * w;
    float cy = an.y + 0.5f * h;
    float pcx = cx + (rg.x * 0.1f) * w;
    float pcy = cy + (rg.y * 0.1f) * h;
    float pw_ = expf(rg.z * 0.2f) * w;
    float ph_ = expf(rg.w * 0.2f) * h;

    float W = pw ? (float)__ldg(pw) : 1024.0f;
    float H = ph ? (float)__ldg(ph) : 1024.0f;

    float x1 = fmaxf(pcx - 0.5f * pw_, 0.0f);
    float y1 = fmaxf(pcy - 0.5f * ph_, 0.0f);
    float x2 = fminf(pcx + 0.5f * pw_, W);
    float y2 = fminf(pcy + 0.5f * ph_, H);

    g_boxes[a] = make_float4(x1, y1, x2, y2);
    g_areas[a] = (x2 - x1) * (y2 - y1);
    g_keys_in[a] = (m > PSTTHD) ? m : -FLT_MAX;
    g_vals_in[a] = a;
}

// ---------------------------------------------------------------------------
// Pairwise suppression masks among top-T0 sorted candidates.
// Thread (i, w) computes 64-bit word w of row i: bit j set iff j < i and
// IoU(cand_i, cand_j) > thr. Full-grid parallel.
// ---------------------------------------------------------------------------
__global__ void pair_kernel(int A)
{
    int tid = blockIdx.x * blockDim.x + threadIdx.x;
    if (tid >= T0 * W0) return;
    int i = tid / W0;
    int w = tid % W0;

    int jbase = w * 64;
    if (jbase >= i || i >= A) {            // row area strictly lower-triangular
        g_mask[i * W0 + w] = 0ULL;
        return;
    }

    int ii = g_vals_out[i];
    float4 bi = g_boxes[ii];
    float  ai = g_areas[ii];

    unsigned long long word = 0ULL;
    int jend = min(jbase + 64, i);
    for (int j = jbase; j < jend; j++) {
        int jj = g_vals_out[j];
        float4 bj = g_boxes[jj];
        float  aj = g_areas[jj];
        if (sup_test(bi.x, bi.y, bi.z, bi.w, ai, bj.x, bj.y, bj.z, bj.w, aj))
            word |= 1ULL << (j - jbase);
    }
    g_mask[i * W0 + w] = word;
}

// ---------------------------------------------------------------------------
// One warp: exact greedy over the top-T0 using the masks. Lane l owns mask
// word l. keptmask accumulates bits of kept sorted-positions.
// ---------------------------------------------------------------------------
__global__ void scan0_kernel(int A)
{
    int lane = threadIdx.x;
    unsigned long long keptmask = 0ULL;
    int nk = 0;
    int Tlim = T0 < A ? T0 : A;

    for (int i = 0; i < Tlim; i++) {
        float key = g_keys_out[i];      // uniform across warp
        if (!(key > PSTTHD)) break;     // sorted desc: nothing valid after
        unsigned long long row = g_mask[i * W0 + lane];
        bool hit = (row & keptmask) != 0ULL;
        if (__any_sync(0xffffffffu, hit)) continue;
        // keep candidate i
        if (lane == (i >> 6)) keptmask |= 1ULL << (i & 63);
        if (lane == 0) {
            int idx = g_vals_out[i];
            g_kbox[nk]  = g_boxes[idx];
            g_karea[nk] = g_areas[idx];
            g_keep[nk]  = idx;
        }
        nk++;
        if (nk >= MAXDET) break;
    }
    if (lane == 0) g_nk = nk;
}

// ---------------------------------------------------------------------------
// Full-grid: flag tail candidates surviving vs the snapshot kept set.
// Emits a ballot bitmap (1 = survivor needing ordered re-check).
// ---------------------------------------------------------------------------
__global__ void flagA_kernel(int A)
{
    __shared__ float4 skb[MAXDET];
    __shared__ float  ska[MAXDET];
    __shared__ int    snk;
    if (threadIdx.x == 0) snk = g_nk;
    __syncthreads();
    int nk = snk;
    for (int k = threadIdx.x; k < nk; k += blockDim.x) {
        skb[k] = g_kbox[k];
        ska[k] = g_karea[k];
    }
    __syncthreads();

    int p = T0 + blockIdx.x * blockDim.x + threadIdx.x;
    bool surv = false;
    if (p < A && nk < MAXDET) {
        float key = g_keys_out[p];
        if (key > PSTTHD) {
            int idx = g_vals_out[p];
            float4 b = g_boxes[idx];
            float ar = g_areas[idx];
            surv = true;
            for (int k = 0; k < nk; k++) {
                if (sup_test(b.x, b.y, b.z, b.w, ar,
                             skb[k].x, skb[k].y, skb[k].z, skb[k].w, ska[k])) {
                    surv = false;
                    break;
                }
            }
        }
    }
    unsigned m = __ballot_sync(0xffffffffu, surv);
    if ((threadIdx.x & 31) == 0) {
        int word = (p - T0) >> 5;
        g_surv[word] = m;
    }
}

// ---------------------------------------------------------------------------
// One warp: walk survivor bitmap in sorted order; each survivor checked only
// against keeps added after the snapshot (lanes parallel over those keeps).
// ---------------------------------------------------------------------------
__global__ void tailB_kernel(int A)
{
    __shared__ float4 s_nb[MAXDET];
    __shared__ float  s_na[MAXDET];
    int lane = threadIdx.x;
    int nk = g_nk;                 // uniform (all lanes read same)
    int snap = nk;
    if (nk >= MAXDET || T0 >= A) { if (lane == 0) g_nk = nk; return; }

    int nwords = (A - T0 + 31) >> 5;
    for (int wb = 0; wb < nwords; wb += 32) {
        unsigned w = 0;
        int wi = wb + lane;
        if (wi < nwords) w = g_surv[wi];
        unsigned act = __ballot_sync(0xffffffffu, w != 0u);
        while (act) {
            int src = __ffs(act) - 1;
            act &= act - 1;
            unsigned word = __shfl_sync(0xffffffffu, w, src);
            int pbase = T0 + ((wb + src) << 5);
            while (word) {
                int b = __ffs(word) - 1;
                word &= word - 1;
                int p = pbase + b;
                int idx = g_vals_out[p];
                float4 bx = g_boxes[idx];
                float ar = g_areas[idx];
                bool hit = false;
                for (int k = snap + lane; k < nk; k += 32) {
                    if (sup_test(bx.x, bx.y, bx.z, bx.w, ar,
                                 s_nb[k - snap].x, s_nb[k - snap].y,
                                 s_nb[k - snap].z, s_nb[k - snap].w, s_na[k - snap]))
                        hit = true;
                }
                if (!__any_sync(0xffffffffu, hit)) {
                    if (lane == 0) {
                        g_kbox[nk]  = bx;
                        g_karea[nk] = ar;
                        g_keep[nk]  = idx;
                        s_nb[nk - snap] = bx;
                        s_na[nk - snap] = ar;
                    }
                    __syncwarp();
                    nk++;
                    if (nk >= MAXDET) { if (lane == 0) g_nk = nk; return; }
                }
            }
        }
    }
    if (lane == 0) g_nk = nk;
}

// ---------------------------------------------------------------------------
// Finalize: per kept slot, argmax over class row (first-max), write output
// tuple: scores[300] | class[300] | boxes[300*4] | valid[300]  (floats)
// ---------------------------------------------------------------------------
__global__ void final_kernel(const float* __restrict__ cls, int C,
                             float* __restrict__ out)
{
    int warp = (blockIdx.x * blockDim.x + threadIdx.x) >> 5;
    int lane = threadIdx.x & 31;
    if (warp >= MAXDET) return;

    int nk = g_nk;
    bool valid = warp < nk;
    float score = 0.f, clsid = -1.f;
    float bx0 = 0.f, bx1 = 0.f, bx2 = 0.f, bx3 = 0.f;

    if (valid) {
        int idx = g_keep[warp];
        const float* row = cls + (size_t)idx * C;
        float best = -FLT_MAX;
        int bi = 0x7fffffff;
        for (int c = lane; c < C; c += 32) {
            float vv = row[c];
            if (vv > best) { best = vv; bi = c; }
        }
        #pragma unroll
        for (int off = 16; off; off >>= 1) {
            float ov = __shfl_down_sync(0xffffffffu, best, off);
            int   oi = __shfl_down_sync(0xffffffffu, bi,   off);
            if (ov > best || (ov == best && oi < bi)) { best = ov; bi = oi; }
        }
        best = __shfl_sync(0xffffffffu, best, 0);
        bi   = __shfl_sync(0xffffffffu, bi,   0);
        score = best;
        clsid = (float)bi;
        float4 b = g_kbox[warp];
        bx0 = b.x; bx1 = b.y; bx2 = b.z; bx3 = b.w;
    }
    if (lane == 0) {
        out[warp]                      = score;
        out[MAXDET + warp]             = clsid;
        out[2 * MAXDET + 4 * warp + 0] = bx0;
        out[2 * MAXDET + 4 * warp + 1] = bx1;
        out[2 * MAXDET + 4 * warp + 2] = bx2;
        out[2 * MAXDET + 4 * warp + 3] = bx3;
        out[6 * MAXDET + warp]         = valid ? 1.0f : 0.0f;
    }
}

// ---------------------------------------------------------------------------
extern "C" void kernel_launch(void* const* d_in, const int* in_sizes, int n_in,
                              void* d_out, int out_size)
{
    const float* cls = (const float*)d_in[0];
    const float* reg = (const float*)d_in[1];
    const float* anc = (const float*)d_in[2];
    const int*   ph  = (n_in > 3) ? (const int*)d_in[3] : nullptr;
    const int*   pw  = (n_in > 4) ? (const int*)d_in[4] : nullptr;

    int A = in_sizes[2] / 4;
    if (A > MAXA) A = MAXA;
    int C = in_sizes[0] / A;

    prep_kernel<<<(A + 255) / 256, 256>>>(cls, reg, anc, ph, pw, A, C);

    void *keys_in, *vals_in, *keys_out, *vals_out, *temp;
    cudaGetSymbolAddress(&keys_in,  g_keys_in);
    cudaGetSymbolAddress(&vals_in,  g_vals_in);
    cudaGetSymbolAddress(&keys_out, g_keys_out);
    cudaGetSymbolAddress(&vals_out, g_vals_out);
    cudaGetSymbolAddress(&temp,     g_sort_temp);

    size_t temp_bytes = 0;
    cub::DeviceRadixSort::SortPairsDescending(
        (void*)nullptr, temp_bytes,
        (const float*)keys_in, (float*)keys_out,
        (const int*)vals_in,   (int*)vals_out, A, 0, 32, (cudaStream_t)0);
    if (temp_bytes > sizeof(g_sort_temp)) temp_bytes = sizeof(g_sort_temp);
    cub::DeviceRadixSort::SortPairsDescending(
        temp, temp_bytes,
        (const float*)keys_in, (float*)keys_out,
        (const int*)vals_in,   (int*)vals_out, A, 0, 32, (cudaStream_t)0);

    pair_kernel<<<(T0 * W0 + 255) / 256, 256>>>(A);
    scan0_kernel<<<1, 32>>>(A);
    if (A > T0) flagA_kernel<<<(A - T0 + 255) / 256, 256>>>(A);
    tailB_kernel<<<1, 32>>>(A);
    final_kernel<<<(MAXDET * 32 + 127) / 128, 128>>>(cls, C, (float*)d_out);
}

// round 3
// speedup vs baseline: 21.1111x; 1.9713x over previous
#include <cuda_runtime.h>
#include <cuda_bf16.h>
#include <cub/cub.cuh>
#include <cfloat>
#include <cstdint>

// ---------------------------------------------------------------------------
// RetinaNet postprocess, round 3.
//   prep2      : fused coalesced decode (thread/anchor) + class-max (warp/anchor)
//   CUB sort   : stable descending radix (score key, anchor idx)
//   gather_top : compact top-T0 candidate boxes/areas
//   pair       : full-grid pairwise IoU masks for top T0
//   scan0      : 1-warp exact greedy, double-buffered prefetch, deferred gathers
//   resolve    : positions -> anchor idx / box / area for kept set
//   flagA      : full-grid tail suppression vs snapshot kept set
//   tailB      : 1-warp ordered walk of survivors vs post-snapshot keeps
//   final      : per-keep class argmax + output tuple
// ---------------------------------------------------------------------------

#define MAXA   262144
#define MAXDET 300
#define T0     2048
#define W0     (T0 / 64)
#define PSTTHD 0.05f
#define NMSTHD 0.5f

__device__ float  g_keys_in [MAXA];
__device__ int    g_vals_in [MAXA];
__device__ float  g_keys_out[MAXA];
__device__ int    g_vals_out[MAXA];
__device__ float4 g_boxes   [MAXA];
__device__ float  g_areas   [MAXA];
__device__ float4 g_cbox    [T0];
__device__ float  g_carea   [T0];
__device__ unsigned long long g_mask[T0 * W0];
__device__ unsigned int       g_surv[(MAXA - T0) / 32 + 32];
__device__ int    g_keeppos[MAXDET];
__device__ float4 g_kbox [MAXDET];
__device__ float  g_karea[MAXDET];
__device__ int    g_keep [MAXDET];
__device__ int    g_nk0;
__device__ int    g_nk;
__device__ unsigned char g_sort_temp[32u << 20];

__device__ __forceinline__ bool sup_test(float x1, float y1, float x2, float y2, float ar,
                                         float X1, float Y1, float X2, float Y2, float AR)
{
    float xx1 = fmaxf(x1, X1);
    float yy1 = fmaxf(y1, Y1);
    float xx2 = fminf(x2, X2);
    float yy2 = fminf(y2, Y2);
    float inter = fmaxf(xx2 - xx1, 0.0f) * fmaxf(yy2 - yy1, 0.0f);
    float iou = inter / (ar + AR - inter + 1e-8f);
    return iou > NMSTHD;
}

// ---------------------------------------------------------------------------
// prep2: warp-per-anchor coalesced class max + thread-per-anchor decode.
// grid = ceil(A/8) blocks of 256 (8 warps). Decode covered by low blocks.
// ---------------------------------------------------------------------------
__global__ void prep2_kernel(const float* __restrict__ cls,
                             const float* __restrict__ reg,
                             const float* __restrict__ anc,
                             const int*   __restrict__ ph,
                             const int*   __restrict__ pw,
                             int A, int C)
{
    int tid  = threadIdx.x;
    int lane = tid & 31;
    int w    = tid >> 5;

    // ---- score: warp per anchor, coalesced strided row read ----
    int a = blockIdx.x * 8 + w;
    if (a < A) {
        const float* row = cls + (size_t)a * C;
        float m = -FLT_MAX;
        for (int c = lane; c < C; c += 32) m = fmaxf(m, row[c]);
        #pragma unroll
        for (int off = 16; off; off >>= 1)
            m = fmaxf(m, __shfl_xor_sync(0xffffffffu, m, off));
        if (lane == 0) {
            g_keys_in[a] = (m > PSTTHD) ? m : 0.0f;   // 0.0 sorts last among valid>=0.05
            g_vals_in[a] = a;
        }
    }

    // ---- decode: thread per anchor, fully coalesced float4 ----
    int a2 = blockIdx.x * blockDim.x + tid;
    if (a2 < A) {
        float4 an = ((const float4*)anc)[a2];
        float4 rg = ((const float4*)reg)[a2];
        float bw = an.z - an.x;
        float bh = an.w - an.y;
        float cx = an.x + 0.5f * bw;
        float cy = an.y + 0.5f * bh;
        float pcx = cx + (rg.x * 0.1f) * bw;
        float pcy = cy + (rg.y * 0.1f) * bh;
        float pw_ = expf(rg.z * 0.2f) * bw;
        float ph_ = expf(rg.w * 0.2f) * bh;

        float W = pw ? (float)__ldg(pw) : 1024.0f;
        float H = ph ? (float)__ldg(ph) : 1024.0f;

        float x1 = fmaxf(pcx - 0.5f * pw_, 0.0f);
        float y1 = fmaxf(pcy - 0.5f * ph_, 0.0f);
        float x2 = fminf(pcx + 0.5f * pw_, W);
        float y2 = fminf(pcy + 0.5f * ph_, H);

        g_boxes[a2] = make_float4(x1, y1, x2, y2);
        g_areas[a2] = (x2 - x1) * (y2 - y1);
    }
}

// ---------------------------------------------------------------------------
__global__ void gather_kernel(int A)
{
    int t = blockIdx.x * blockDim.x + threadIdx.x;
    if (t >= T0) return;
    if (t < A) {
        int idx = g_vals_out[t];
        g_cbox[t]  = g_boxes[idx];
        g_carea[t] = g_areas[idx];
    } else {
        g_cbox[t]  = make_float4(0.f, 0.f, 0.f, 0.f);
        g_carea[t] = 0.f;
    }
}

// ---------------------------------------------------------------------------
__global__ void pair_kernel(int A)
{
    int tid = blockIdx.x * blockDim.x + threadIdx.x;
    if (tid >= T0 * W0) return;
    int i = tid / W0;
    int w = tid % W0;

    int jbase = w * 64;
    if (jbase >= i || i >= A) {
        g_mask[i * W0 + w] = 0ULL;
        return;
    }

    float4 bi = g_cbox[i];
    float  ai = g_carea[i];

    unsigned long long word = 0ULL;
    int jend = min(jbase + 64, i);
    for (int j = jbase; j < jend; j++) {
        float4 bj = g_cbox[j];
        float  aj = g_carea[j];
        if (sup_test(bi.x, bi.y, bi.z, bi.w, ai, bj.x, bj.y, bj.z, bj.w, aj))
            word |= 1ULL << (j - jbase);
    }
    g_mask[i * W0 + w] = word;
}

// ---------------------------------------------------------------------------
// scan0: 1 warp, exact greedy over top T0 with double-buffered mask prefetch.
// ---------------------------------------------------------------------------
__device__ __forceinline__ void load_chunk(unsigned long long (&b)[16],
                                           int base, int Tlim, int lane)
{
    #pragma unroll
    for (int r = 0; r < 16; r++) {
        int i = base + r;
        b[r] = (i < Tlim) ? g_mask[(size_t)i * W0 + lane] : 0ULL;
    }
}

__device__ __forceinline__ void scan_chunk(const unsigned long long (&buf)[16],
                                           int base0, int shfl_off, float myk,
                                           int Tlim, unsigned long long &kept,
                                           int &nk, bool &done, int lane)
{
    #pragma unroll
    for (int r = 0; r < 16; r++) {
        int i = base0 + r;
        if (i >= Tlim) { done = true; break; }
        float key = __shfl_sync(0xffffffffu, myk, shfl_off + r);
        if (!(key > PSTTHD)) { done = true; break; }
        bool hit = (buf[r] & kept) != 0ULL;
        if (!__any_sync(0xffffffffu, hit)) {
            if (lane == (i >> 6)) kept |= 1ULL << (i & 63);
            if (lane == 0) g_keeppos[nk] = i;     // fire-and-forget store
            nk++;
            if (nk >= MAXDET) { done = true; break; }
        }
    }
}

__global__ void scan0_kernel(int A)
{
    int lane = threadIdx.x;
    int Tlim = T0 < A ? T0 : A;
    unsigned long long kept = 0ULL;
    int nk = 0;
    bool done = false;

    unsigned long long bufA[16], bufB[16];
    load_chunk(bufA, 0, Tlim, lane);

    for (int base = 0; base < Tlim && !done; base += 32) {
        load_chunk(bufB, base + 16, Tlim, lane);
        int ki = base + lane;
        float myk = (ki < Tlim) ? g_keys_out[ki] : 0.0f;
        scan_chunk(bufA, base, 0, myk, Tlim, kept, nk, done, lane);
        if (done) break;
        load_chunk(bufA, base + 32, Tlim, lane);
        scan_chunk(bufB, base + 16, 16, myk, Tlim, kept, nk, done, lane);
    }
    if (lane == 0) g_nk0 = nk;
}

// ---------------------------------------------------------------------------
__global__ void resolve_kernel()
{
    int t = threadIdx.x;
    int nk = g_nk0;
    if (t < nk) {
        int pos = g_keeppos[t];
        int idx = g_vals_out[pos];
        g_keep[t]  = idx;
        g_kbox[t]  = g_boxes[idx];
        g_karea[t] = g_areas[idx];
    }
    if (t == 0) g_nk = nk;
}

// ---------------------------------------------------------------------------
__global__ void flagA_kernel(int A)
{
    __shared__ float4 skb[MAXDET];
    __shared__ float  ska[MAXDET];
    __shared__ int    snk;
    if (threadIdx.x == 0) snk = g_nk;
    __syncthreads();
    int nk = snk;
    for (int k = threadIdx.x; k < nk; k += blockDim.x) {
        skb[k] = g_kbox[k];
        ska[k] = g_karea[k];
    }
    __syncthreads();

    int p = T0 + blockIdx.x * blockDim.x + threadIdx.x;
    bool surv = false;
    if (p < A && nk < MAXDET) {
        float key = g_keys_out[p];
        if (key > PSTTHD) {
            int idx = g_vals_out[p];
            float4 b = g_boxes[idx];
            float ar = g_areas[idx];
            surv = true;
            for (int k = 0; k < nk; k++) {
                if (sup_test(b.x, b.y, b.z, b.w, ar,
                             skb[k].x, skb[k].y, skb[k].z, skb[k].w, ska[k])) {
                    surv = false;
                    break;
                }
            }
        }
    }
    unsigned m = __ballot_sync(0xffffffffu, surv);
    if ((threadIdx.x & 31) == 0) {
        int word = (p - T0) >> 5;
        g_surv[word] = m;
    }
}

// ---------------------------------------------------------------------------
__global__ void tailB_kernel(int A)
{
    __shared__ float4 s_nb[MAXDET];
    __shared__ float  s_na[MAXDET];
    int lane = threadIdx.x;
    int nk = g_nk;
    int snap = nk;
    if (nk >= MAXDET || T0 >= A) { if (lane == 0) g_nk = nk; return; }

    int nwords = (A - T0 + 31) >> 5;
    for (int wb = 0; wb < nwords; wb += 32) {
        unsigned w = 0;
        int wi = wb + lane;
        if (wi < nwords) w = g_surv[wi];
        unsigned act = __ballot_sync(0xffffffffu, w != 0u);
        while (act) {
            int src = __ffs(act) - 1;
            act &= act - 1;
            unsigned word = __shfl_sync(0xffffffffu, w, src);
            int pbase = T0 + ((wb + src) << 5);
            while (word) {
                int b = __ffs(word) - 1;
                word &= word - 1;
                int p = pbase + b;
                int idx = g_vals_out[p];
                float4 bx = g_boxes[idx];
                float ar = g_areas[idx];
                bool hit = false;
                for (int k = snap + lane; k < nk; k += 32) {
                    if (sup_test(bx.x, bx.y, bx.z, bx.w, ar,
                                 s_nb[k - snap].x, s_nb[k - snap].y,
                                 s_nb[k - snap].z, s_nb[k - snap].w, s_na[k - snap]))
                        hit = true;
                }
                if (!__any_sync(0xffffffffu, hit)) {
                    if (lane == 0) {
                        g_kbox[nk]  = bx;
                        g_karea[nk] = ar;
                        g_keep[nk]  = idx;
                        s_nb[nk - snap] = bx;
                        s_na[nk - snap] = ar;
                    }
                    __syncwarp();
                    nk++;
                    if (nk >= MAXDET) { if (lane == 0) g_nk = nk; return; }
                }
            }
        }
    }
    if (lane == 0) g_nk = nk;
}

// ---------------------------------------------------------------------------
__global__ void final_kernel(const float* __restrict__ cls, int C,
                             float* __restrict__ out)
{
    int warp = (blockIdx.x * blockDim.x + threadIdx.x) >> 5;
    int lane = threadIdx.x & 31;
    if (warp >= MAXDET) return;

    int nk = g_nk;
    bool valid = warp < nk;
    float score = 0.f, clsid = -1.f;
    float bx0 = 0.f, bx1 = 0.f, bx2 = 0.f, bx3 = 0.f;

    if (valid) {
        int idx = g_keep[warp];
        const float* row = cls + (size_t)idx * C;
        float best = -FLT_MAX;
        int bi = 0x7fffffff;
        for (int c = lane; c < C; c += 32) {
            float vv = row[c];
            if (vv > best) { best = vv; bi = c; }
        }
        #pragma unroll
        for (int off = 16; off; off >>= 1) {
            float ov = __shfl_down_sync(0xffffffffu, best, off);
            int   oi = __shfl_down_sync(0xffffffffu, bi,   off);
            if (ov > best || (ov == best && oi < bi)) { best = ov; bi = oi; }
        }
        best = __shfl_sync(0xffffffffu, best, 0);
        bi   = __shfl_sync(0xffffffffu, bi,   0);
        score = best;
        clsid = (float)bi;
        float4 b = g_kbox[warp];
        bx0 = b.x; bx1 = b.y; bx2 = b.z; bx3 = b.w;
    }
    if (lane == 0) {
        out[warp]                      = score;
        out[MAXDET + warp]             = clsid;
        out[2 * MAXDET + 4 * warp + 0] = bx0;
        out[2 * MAXDET + 4 * warp + 1] = bx1;
        out[2 * MAXDET + 4 * warp + 2] = bx2;
        out[2 * MAXDET + 4 * warp + 3] = bx3;
        out[6 * MAXDET + warp]         = valid ? 1.0f : 0.0f;
    }
}

// ---------------------------------------------------------------------------
extern "C" void kernel_launch(void* const* d_in, const int* in_sizes, int n_in,
                              void* d_out, int out_size)
{
    const float* cls = (const float*)d_in[0];
    const float* reg = (const float*)d_in[1];
    const float* anc = (const float*)d_in[2];
    const int*   ph  = (n_in > 3) ? (const int*)d_in[3] : nullptr;
    const int*   pw  = (n_in > 4) ? (const int*)d_in[4] : nullptr;

    int A = in_sizes[2] / 4;
    if (A > MAXA) A = MAXA;
    int C = in_sizes[0] / A;

    prep2_kernel<<<(A + 7) / 8, 256>>>(cls, reg, anc, ph, pw, A, C);

    void *keys_in, *vals_in, *keys_out, *vals_out, *temp;
    cudaGetSymbolAddress(&keys_in,  g_keys_in);
    cudaGetSymbolAddress(&vals_in,  g_vals_in);
    cudaGetSymbolAddress(&keys_out, g_keys_out);
    cudaGetSymbolAddress(&vals_out, g_vals_out);
    cudaGetSymbolAddress(&temp,     g_sort_temp);

    size_t temp_bytes = 0;
    cub::DeviceRadixSort::SortPairsDescending(
        (void*)nullptr, temp_bytes,
        (const float*)keys_in, (float*)keys_out,
        (const int*)vals_in,   (int*)vals_out, A, 0, 32, (cudaStream_t)0);
    if (temp_bytes > sizeof(g_sort_temp)) temp_bytes = sizeof(g_sort_temp);
    cub::DeviceRadixSort::SortPairsDescending(
        temp, temp_bytes,
        (const float*)keys_in, (float*)keys_out,
        (const int*)vals_in,   (int*)vals_out, A, 0, 32, (cudaStream_t)0);

    gather_kernel<<<(T0 + 255) / 256, 256>>>(A);
    pair_kernel<<<(T0 * W0 + 255) / 256, 256>>>(A);
    scan0_kernel<<<1, 32>>>(A);
    resolve_kernel<<<1, 320>>>();
    if (A > T0) flagA_kernel<<<(A - T0 + 255) / 256, 256>>>(A);
    tailB_kernel<<<1, 32>>>(A);
    final_kernel<<<(MAXDET * 32 + 127) / 128, 128>>>(cls, C, (float*)d_out);
}

// round 4
// speedup vs baseline: 27.5814x; 1.3065x over previous
#include <cuda_runtime.h>
#include <cuda_bf16.h>
#include <cub/cub.cuh>
#include <cfloat>
#include <cstdint>

// ---------------------------------------------------------------------------
// RetinaNet postprocess, round 4: no device-wide sort.
//   zero    : reset histogram + counters
//   prep2   : decode (thread/anchor) + class-max (warp/anchor) + score histogram
//   scanB   : pick score-bit slab boundary with |slab| <= T0
//   compact : gather slab members as 48-bit (score,~idx) keys
//   sorttop : one-block radix sort of slab, gather boxes into compact arrays
//   pair    : full-grid pairwise IoU masks over sorted slab
//   scan0   : 1-warp exact greedy over slab (double-buffered masks)
//   resolve : kept positions -> anchor idx/box/area
//   flagA   : order-free tail suppression vs snapshot; append survivors
//   tailC   : reference argmax+suppress loop over survivors (exact)
//   final   : per-keep class argmax + output tuple
// Exactness: slab cut is a clean cut in descending (score, idx) order; greedy
// order = sort(slab) ++ sort(tail); tail handled exactly by snapshot flags +
// serial greedy over survivors (kept set monotone).
// ---------------------------------------------------------------------------

#define MAXA   262144
#define MAXDET 300
#define T0     2048
#define W0     (T0 / 64)
#define NBKT   65536
#define CAP    65536
#define PSTTHD 0.05f
#define NMSTHD 0.5f

__device__ float  g_keys_in[MAXA];
__device__ float4 g_boxes  [MAXA];
__device__ float  g_areas  [MAXA];
__device__ unsigned int g_hist[NBKT];
__device__ unsigned long long g_ckeys[T0];
__device__ int    g_cidx [T0];
__device__ float4 g_cbox [T0];
__device__ float  g_carea[T0];
__device__ unsigned long long g_mask[T0 * W0];
__device__ unsigned long long g_skey[CAP];
__device__ int    g_keeppos[MAXDET];
__device__ float4 g_kbox [MAXDET];
__device__ float  g_karea[MAXDET];
__device__ int    g_keep [MAXDET];
__device__ int    g_boundary;
__device__ int    g_scnt;
__device__ int    g_T;
__device__ int    g_nsurv;
__device__ int    g_nk0;
__device__ int    g_nk;

__device__ __forceinline__ bool sup_test(float x1, float y1, float x2, float y2, float ar,
                                         float X1, float Y1, float X2, float Y2, float AR)
{
    float xx1 = fmaxf(x1, X1);
    float yy1 = fmaxf(y1, Y1);
    float xx2 = fminf(x2, X2);
    float yy2 = fminf(y2, Y2);
    float inter = fmaxf(xx2 - xx1, 0.0f) * fmaxf(yy2 - yy1, 0.0f);
    float iou = inter / (ar + AR - inter + 1e-8f);
    return iou > NMSTHD;
}

__device__ __forceinline__ unsigned rbucket(unsigned bits)
{
    unsigned rb = (0x3F800000u - bits) >> 8;
    return rb > (NBKT - 1u) ? (NBKT - 1u) : rb;
}

// ---------------------------------------------------------------------------
__global__ void zero_kernel()
{
    int t = blockIdx.x * blockDim.x + threadIdx.x;
    if (t < NBKT) g_hist[t] = 0u;
    if (t == 0) { g_scnt = 0; g_nsurv = 0; g_T = 0; g_boundary = -1; }
}

// ---------------------------------------------------------------------------
__global__ void prep2_kernel(const float* __restrict__ cls,
                             const float* __restrict__ reg,
                             const float* __restrict__ anc,
                             const int*   __restrict__ ph,
                             const int*   __restrict__ pw,
                             int A, int C)
{
    int tid  = threadIdx.x;
    int lane = tid & 31;
    int w    = tid >> 5;

    int a = blockIdx.x * 8 + w;
    if (a < A) {
        const float* row = cls + (size_t)a * C;
        float m = -FLT_MAX;
        for (int c = lane; c < C; c += 32) m = fmaxf(m, row[c]);
        #pragma unroll
        for (int off = 16; off; off >>= 1)
            m = fmaxf(m, __shfl_xor_sync(0xffffffffu, m, off));
        if (lane == 0) {
            bool valid = m > PSTTHD;
            g_keys_in[a] = valid ? m : 0.0f;
            if (valid) atomicAdd(&g_hist[rbucket(__float_as_uint(m))], 1u);
        }
    }

    int a2 = blockIdx.x * blockDim.x + tid;
    if (a2 < A) {
        float4 an = ((const float4*)anc)[a2];
        float4 rg = ((const float4*)reg)[a2];
        float bw = an.z - an.x;
        float bh = an.w - an.y;
        float cx = an.x + 0.5f * bw;
        float cy = an.y + 0.5f * bh;
        float pcx = cx + (rg.x * 0.1f) * bw;
        float pcy = cy + (rg.y * 0.1f) * bh;
        float pw_ = expf(rg.z * 0.2f) * bw;
        float ph_ = expf(rg.w * 0.2f) * bh;

        float W = pw ? (float)__ldg(pw) : 1024.0f;
        float H = ph ? (float)__ldg(ph) : 1024.0f;

        float x1 = fmaxf(pcx - 0.5f * pw_, 0.0f);
        float y1 = fmaxf(pcy - 0.5f * ph_, 0.0f);
        float x2 = fminf(pcx + 0.5f * pw_, W);
        float y2 = fminf(pcy + 0.5f * ph_, H);

        g_boxes[a2] = make_float4(x1, y1, x2, y2);
        g_areas[a2] = (x2 - x1) * (y2 - y1);
    }
}

// ---------------------------------------------------------------------------
// One block: largest boundary B such that sum(hist[0..B]) <= T0.
// ---------------------------------------------------------------------------
__global__ void scanB_kernel()
{
    __shared__ unsigned sc[1024];
    __shared__ int crossed;
    int t = threadIdx.x;
    if (t == 0) crossed = 0;
    __syncthreads();

    unsigned running = 0;
    for (int c = 0; c < NBKT / 1024; c++) {
        sc[t] = g_hist[c * 1024 + t];
        __syncthreads();
        for (int off = 1; off < 1024; off <<= 1) {
            unsigned x = (t >= off) ? sc[t - off] : 0u;
            __syncthreads();
            sc[t] += x;
            __syncthreads();
        }
        unsigned total = sc[1023];
        unsigned R = T0 - running;
        if (total <= R) { running += total; __syncthreads(); continue; }

        unsigned incl = sc[t];
        if (incl <= R && (t == 1023 || sc[t + 1] > R)) {
            g_boundary = c * 1024 + t;
            g_T = (int)(running + incl);
        }
        if (t == 0 && sc[0] > R) {
            g_boundary = c * 1024 - 1;
            g_T = (int)running;
        }
        if (t == 0) crossed = 1;
        __syncthreads();
        break;
    }
    if (!crossed && t == 0) {
        g_boundary = NBKT - 1;
        g_T = (int)running;
    }
}

// ---------------------------------------------------------------------------
__global__ void compact_kernel(int A)
{
    int a = blockIdx.x * blockDim.x + threadIdx.x;
    if (a >= A) return;
    float k = g_keys_in[a];
    if (!(k > PSTTHD)) return;
    unsigned bits = __float_as_uint(k);
    if ((int)rbucket(bits) <= g_boundary) {
        int p = atomicAdd(&g_scnt, 1);
        g_ckeys[p] = ((unsigned long long)bits << 18) |
                     (unsigned long long)(0x3FFFFu - (unsigned)a);
    }
}

// ---------------------------------------------------------------------------
// One block: sort slab keys descending, gather boxes into compact arrays.
// ---------------------------------------------------------------------------
__global__ void sorttop_kernel()
{
    using BRS = cub::BlockRadixSort<unsigned long long, 1024, 2>;
    __shared__ typename BRS::TempStorage ts;
    int t = threadIdx.x;
    int n = g_scnt;

    unsigned long long k[2];
    #pragma unroll
    for (int j = 0; j < 2; j++) {
        int i = t * 2 + j;
        k[j] = (i < n) ? g_ckeys[i] : 0ULL;
    }
    BRS(ts).SortDescending(k, 0, 48);

    #pragma unroll
    for (int j = 0; j < 2; j++) {
        int i = t * 2 + j;
        if (i < n) {
            int a = (int)(0x3FFFFu - (unsigned)(k[j] & 0x3FFFFULL));
            g_cidx[i]  = a;
            g_cbox[i]  = g_boxes[a];
            g_carea[i] = g_areas[a];
        }
    }
}

// ---------------------------------------------------------------------------
__global__ void pair_kernel()
{
    int tid = blockIdx.x * blockDim.x + threadIdx.x;
    if (tid >= T0 * W0) return;
    int i = tid / W0;
    int w = tid % W0;
    int T = g_T;

    int jbase = w * 64;
    if (jbase >= i || i >= T) {
        g_mask[i * W0 + w] = 0ULL;
        return;
    }

    float4 bi = g_cbox[i];
    float  ai = g_carea[i];

    unsigned long long word = 0ULL;
    int jend = min(jbase + 64, i);
    for (int j = jbase; j < jend; j++) {
        float4 bj = g_cbox[j];
        float  aj = g_carea[j];
        if (sup_test(bi.x, bi.y, bi.z, bi.w, ai, bj.x, bj.y, bj.z, bj.w, aj))
            word |= 1ULL << (j - jbase);
    }
    g_mask[i * W0 + w] = word;
}

// ---------------------------------------------------------------------------
__device__ __forceinline__ void load_chunk(unsigned long long (&b)[16],
                                           int base, int Tlim, int lane)
{
    #pragma unroll
    for (int r = 0; r < 16; r++) {
        int i = base + r;
        b[r] = (i < Tlim) ? g_mask[(size_t)i * W0 + lane] : 0ULL;
    }
}

__device__ __forceinline__ void scan_chunk(const unsigned long long (&buf)[16],
                                           int base0, int Tlim,
                                           unsigned long long &kept,
                                           int &nk, bool &done, int lane)
{
    #pragma unroll
    for (int r = 0; r < 16; r++) {
        int i = base0 + r;
        if (i >= Tlim) { done = true; break; }
        bool hit = (buf[r] & kept) != 0ULL;
        if (!__any_sync(0xffffffffu, hit)) {
            if (lane == (i >> 6)) kept |= 1ULL << (i & 63);
            if (lane == 0) g_keeppos[nk] = i;
            nk++;
            if (nk >= MAXDET) { done = true; break; }
        }
    }
}

__global__ void scan0_kernel()
{
    int lane = threadIdx.x;
    int Tlim = g_T;
    unsigned long long kept = 0ULL;
    int nk = 0;
    bool done = false;

    unsigned long long bufA[16], bufB[16];
    load_chunk(bufA, 0, Tlim, lane);

    for (int base = 0; base < Tlim && !done; base += 32) {
        load_chunk(bufB, base + 16, Tlim, lane);
        scan_chunk(bufA, base, Tlim, kept, nk, done, lane);
        if (done) break;
        load_chunk(bufA, base + 32, Tlim, lane);
        scan_chunk(bufB, base + 16, Tlim, kept, nk, done, lane);
    }
    if (lane == 0) g_nk0 = nk;
}

// ---------------------------------------------------------------------------
__global__ void resolve_kernel()
{
    int t = threadIdx.x;
    int nk = g_nk0;
    if (t < nk) {
        int pos = g_keeppos[t];
        int idx = g_cidx[pos];
        g_keep[t]  = idx;
        g_kbox[t]  = g_boxes[idx];
        g_karea[t] = g_areas[idx];
    }
    if (t == 0) g_nk = nk;
}

// ---------------------------------------------------------------------------
// Tail: test every non-slab valid anchor vs snapshot kept set; survivors
// appended (unordered) for tailC.
// ---------------------------------------------------------------------------
__global__ void flagA_kernel(int A)
{
    __shared__ float4 skb[MAXDET];
    __shared__ float  ska[MAXDET];
    __shared__ int    snk;
    if (threadIdx.x == 0) snk = g_nk;
    __syncthreads();
    int nk = snk;
    if (nk >= MAXDET) return;
    for (int k = threadIdx.x; k < nk; k += blockDim.x) {
        skb[k] = g_kbox[k];
        ska[k] = g_karea[k];
    }
    __syncthreads();

    int a = blockIdx.x * blockDim.x + threadIdx.x;
    if (a >= A) return;
    float key = g_keys_in[a];
    if (!(key > PSTTHD)) return;
    unsigned bits = __float_as_uint(key);
    if ((int)rbucket(bits) <= g_boundary) return;   // slab member, already done

    float4 b = g_boxes[a];
    float ar = g_areas[a];
    for (int k = 0; k < nk; k++) {
        if (sup_test(b.x, b.y, b.z, b.w, ar,
                     skb[k].x, skb[k].y, skb[k].z, skb[k].w, ska[k]))
            return;
    }
    int p = atomicAdd(&g_nsurv, 1);
    if (p < CAP)
        g_skey[p] = ((unsigned long long)bits << 18) |
                    (unsigned long long)(0x3FFFFu - (unsigned)a);
}

// ---------------------------------------------------------------------------
// Reference argmax+suppress loop restricted to survivors. Exact.
// ---------------------------------------------------------------------------
__global__ void tailC_kernel()
{
    __shared__ unsigned long long sb[1024];
    __shared__ int sbi[1024];
    __shared__ float4 swin;
    __shared__ float  swar;
    int t = threadIdx.x;
    int nk = g_nk;
    int ns = min(g_nsurv, CAP);

    if (nk < MAXDET && ns > 0) {
        while (true) {
            unsigned long long best = 0ULL;
            int bi = -1;
            for (int i = t; i < ns; i += 1024) {
                unsigned long long v = g_skey[i];
                if (v > best) { best = v; bi = i; }
            }
            sb[t] = best; sbi[t] = bi;
            __syncthreads();
            for (int off = 512; off; off >>= 1) {
                if (t < off && sb[t + off] > sb[t]) {
                    sb[t] = sb[t + off];
                    sbi[t] = sbi[t + off];
                }
                __syncthreads();
            }
            if (sb[0] == 0ULL) break;

            if (t == 0) {
                int a = (int)(0x3FFFFu - (unsigned)(sb[0] & 0x3FFFFULL));
                float4 b = g_boxes[a];
                float ar = g_areas[a];
                g_keep[nk]  = a;
                g_kbox[nk]  = b;
                g_karea[nk] = ar;
                swin = b; swar = ar;
            }
            __syncthreads();
            float4 wb = swin;
            float war = swar;
            for (int i = t; i < ns; i += 1024) {
                unsigned long long v = g_skey[i];
                if (v != 0ULL) {
                    int a = (int)(0x3FFFFu - (unsigned)(v & 0x3FFFFULL));
                    float4 b = g_boxes[a];
                    if (sup_test(b.x, b.y, b.z, b.w, g_areas[a],
                                 wb.x, wb.y, wb.z, wb.w, war))
                        g_skey[i] = 0ULL;
                }
            }
            nk++;
            if (nk >= MAXDET) break;
            __syncthreads();
        }
    }
    if (t == 0) g_nk = nk;
}

// ---------------------------------------------------------------------------
__global__ void final_kernel(const float* __restrict__ cls, int C,
                             float* __restrict__ out)
{
    int warp = (blockIdx.x * blockDim.x + threadIdx.x) >> 5;
    int lane = threadIdx.x & 31;
    if (warp >= MAXDET) return;

    int nk = g_nk;
    bool valid = warp < nk;
    float score = 0.f, clsid = -1.f;
    float bx0 = 0.f, bx1 = 0.f, bx2 = 0.f, bx3 = 0.f;

    if (valid) {
        int idx = g_keep[warp];
        const float* row = cls + (size_t)idx * C;
        float best = -FLT_MAX;
        int bi = 0x7fffffff;
        for (int c = lane; c < C; c += 32) {
            float vv = row[c];
            if (vv > best) { best = vv; bi = c; }
        }
        #pragma unroll
        for (int off = 16; off; off >>= 1) {
            float ov = __shfl_down_sync(0xffffffffu, best, off);
            int   oi = __shfl_down_sync(0xffffffffu, bi,   off);
            if (ov > best || (ov == best && oi < bi)) { best = ov; bi = oi; }
        }
        best = __shfl_sync(0xffffffffu, best, 0);
        bi   = __shfl_sync(0xffffffffu, bi,   0);
        score = best;
        clsid = (float)bi;
        float4 b = g_kbox[warp];
        bx0 = b.x; bx1 = b.y; bx2 = b.z; bx3 = b.w;
    }
    if (lane == 0) {
        out[warp]                      = score;
        out[MAXDET + warp]             = clsid;
        out[2 * MAXDET + 4 * warp + 0] = bx0;
        out[2 * MAXDET + 4 * warp + 1] = bx1;
        out[2 * MAXDET + 4 * warp + 2] = bx2;
        out[2 * MAXDET + 4 * warp + 3] = bx3;
        out[6 * MAXDET + warp]         = valid ? 1.0f : 0.0f;
    }
}

// ---------------------------------------------------------------------------
extern "C" void kernel_launch(void* const* d_in, const int* in_sizes, int n_in,
                              void* d_out, int out_size)
{
    const float* cls = (const float*)d_in[0];
    const float* reg = (const float*)d_in[1];
    const float* anc = (const float*)d_in[2];
    const int*   ph  = (n_in > 3) ? (const int*)d_in[3] : nullptr;
    const int*   pw  = (n_in > 4) ? (const int*)d_in[4] : nullptr;

    int A = in_sizes[2] / 4;
    if (A > MAXA) A = MAXA;
    int C = in_sizes[0] / A;

    zero_kernel<<<NBKT / 1024, 1024>>>();
    prep2_kernel<<<(A + 7) / 8, 256>>>(cls, reg, anc, ph, pw, A, C);
    scanB_kernel<<<1, 1024>>>();
    compact_kernel<<<(A + 255) / 256, 256>>>(A);
    sorttop_kernel<<<1, 1024>>>();
    pair_kernel<<<(T0 * W0 + 255) / 256, 256>>>();
    scan0_kernel<<<1, 32>>>();
    resolve_kernel<<<1, 320>>>();
    flagA_kernel<<<(A + 255) / 256, 256>>>(A);
    tailC_kernel<<<1, 1024>>>();
    final_kernel<<<(MAXDET * 32 + 127) / 128, 128>>>(cls, C, (float*)d_out);
}

// round 5
// speedup vs baseline: 32.0786x; 1.1631x over previous
#include <cuda_runtime.h>
#include <cuda_bf16.h>
#include <cfloat>
#include <cstdint>

// ---------------------------------------------------------------------------
// RetinaNet postprocess, round 5.
//   zero    : reset histogram + counters
//   prep2   : decode (thread/anchor) + class-max (warp/4 anchors) + histogram
//   scanB   : score-bit slab boundary with |slab| <= T0 (=1024)
//   compact : float4-vectorized gather of slab members as 48-bit keys
//   rank    : one block; rank = #{keys greater}; scatter to sorted arrays
//   pair    : full-grid pairwise IoU masks over sorted slab
//   scan0   : 1-warp exact greedy + fused resolve of kept set
//   flagA   : order-free tail suppression vs snapshot (early-exit @300)
//   tailC   : reference argmax+suppress loop over survivors (exact)
//   final   : per-keep class argmax + output tuple
// ---------------------------------------------------------------------------

#define MAXA   262144
#define MAXDET 300
#define T0     1024
#define W0     (T0 / 64)          // 16 mask words per row
#define NBKT   65536
#define CAP    65536
#define PSTTHD 0.05f
#define NMSTHD 0.5f

__device__ float  g_keys_in[MAXA];
__device__ float4 g_boxes  [MAXA];
__device__ float  g_areas  [MAXA];
__device__ unsigned int g_hist[NBKT];
__device__ unsigned long long g_ckeys[T0];
__device__ int    g_cidx [T0];
__device__ float4 g_cbox [T0];
__device__ float  g_carea[T0];
__device__ unsigned long long g_mask[T0 * W0];
__device__ unsigned long long g_skey[CAP];
__device__ float4 g_kbox [MAXDET];
__device__ float  g_karea[MAXDET];
__device__ int    g_keep [MAXDET];
__device__ int    g_boundary;
__device__ int    g_scnt;
__device__ int    g_T;
__device__ int    g_nsurv;
__device__ int    g_nk;

__device__ __forceinline__ bool sup_test(float x1, float y1, float x2, float y2, float ar,
                                         float X1, float Y1, float X2, float Y2, float AR)
{
    float xx1 = fmaxf(x1, X1);
    float yy1 = fmaxf(y1, Y1);
    float xx2 = fminf(x2, X2);
    float yy2 = fminf(y2, Y2);
    float inter = fmaxf(xx2 - xx1, 0.0f) * fmaxf(yy2 - yy1, 0.0f);
    float iou = inter / (ar + AR - inter + 1e-8f);
    return iou > NMSTHD;
}

__device__ __forceinline__ unsigned rbucket(unsigned bits)
{
    unsigned rb = (0x3F800000u - bits) >> 8;
    return rb > (NBKT - 1u) ? (NBKT - 1u) : rb;
}

// ---------------------------------------------------------------------------
__global__ void zero_kernel()
{
    int t = blockIdx.x * blockDim.x + threadIdx.x;
    if (t < NBKT) g_hist[t] = 0u;
    if (t == 0) { g_scnt = 0; g_nsurv = 0; g_T = 0; g_boundary = -1; }
}

// ---------------------------------------------------------------------------
// prep2: 8 warps/block; each warp scores 4 anchors (MLP), thread/anchor decode.
// grid = ceil(A/32) blocks.
// ---------------------------------------------------------------------------
__global__ void prep2_kernel(const float* __restrict__ cls,
                             const float* __restrict__ reg,
                             const float* __restrict__ anc,
                             const int*   __restrict__ ph,
                             const int*   __restrict__ pw,
                             int A, int C)
{
    int tid  = threadIdx.x;
    int lane = tid & 31;
    int w    = tid >> 5;

    int abase = (blockIdx.x * 8 + w) * 4;
    float mx[4] = {-FLT_MAX, -FLT_MAX, -FLT_MAX, -FLT_MAX};
    #pragma unroll
    for (int r = 0; r < 4; r++) {
        int a = abase + r;
        if (a < A) {
            const float* row = cls + (size_t)a * C;
            for (int c = lane; c < C; c += 32) mx[r] = fmaxf(mx[r], row[c]);
        }
    }
    #pragma unroll
    for (int r = 0; r < 4; r++) {
        float m = mx[r];
        #pragma unroll
        for (int off = 16; off; off >>= 1)
            m = fmaxf(m, __shfl_xor_sync(0xffffffffu, m, off));
        int a = abase + r;
        if (lane == 0 && a < A) {
            bool valid = m > PSTTHD;
            g_keys_in[a] = valid ? m : 0.0f;
            if (valid) atomicAdd(&g_hist[rbucket(__float_as_uint(m))], 1u);
        }
    }

    int a2 = blockIdx.x * blockDim.x + tid;
    if (a2 < A) {
        float4 an = ((const float4*)anc)[a2];
        float4 rg = ((const float4*)reg)[a2];
        float bw = an.z - an.x;
        float bh = an.w - an.y;
        float cx = an.x + 0.5f * bw;
        float cy = an.y + 0.5f * bh;
        float pcx = cx + (rg.x * 0.1f) * bw;
        float pcy = cy + (rg.y * 0.1f) * bh;
        float pw_ = expf(rg.z * 0.2f) * bw;
        float ph_ = expf(rg.w * 0.2f) * bh;

        float W = pw ? (float)__ldg(pw) : 1024.0f;
        float H = ph ? (float)__ldg(ph) : 1024.0f;

        float x1 = fmaxf(pcx - 0.5f * pw_, 0.0f);
        float y1 = fmaxf(pcy - 0.5f * ph_, 0.0f);
        float x2 = fminf(pcx + 0.5f * pw_, W);
        float y2 = fminf(pcy + 0.5f * ph_, H);

        g_boxes[a2] = make_float4(x1, y1, x2, y2);
        g_areas[a2] = (x2 - x1) * (y2 - y1);
    }
}

// ---------------------------------------------------------------------------
// One block: largest boundary B with sum(hist[0..B]) <= T0.
// ---------------------------------------------------------------------------
__global__ void scanB_kernel()
{
    __shared__ unsigned sc[1024];
    __shared__ int crossed;
    int t = threadIdx.x;
    if (t == 0) crossed = 0;
    __syncthreads();

    unsigned running = 0;
    for (int c = 0; c < NBKT / 1024; c++) {
        sc[t] = g_hist[c * 1024 + t];
        __syncthreads();
        for (int off = 1; off < 1024; off <<= 1) {
            unsigned x = (t >= off) ? sc[t - off] : 0u;
            __syncthreads();
            sc[t] += x;
            __syncthreads();
        }
        unsigned total = sc[1023];
        unsigned R = T0 - running;
        if (total <= R) { running += total; __syncthreads(); continue; }

        unsigned incl = sc[t];
        if (incl <= R && (t == 1023 || sc[t + 1] > R)) {
            g_boundary = c * 1024 + t;
            g_T = (int)(running + incl);
        }
        if (t == 0 && sc[0] > R) {
            g_boundary = c * 1024 - 1;
            g_T = (int)running;
        }
        if (t == 0) crossed = 1;
        __syncthreads();
        break;
    }
    if (!crossed && t == 0) {
        g_boundary = NBKT - 1;
        g_T = (int)running;
    }
}

// ---------------------------------------------------------------------------
// Vectorized slab compaction: 4 anchors/thread via float4.
// ---------------------------------------------------------------------------
__global__ void compact_kernel(int A)
{
    int q = blockIdx.x * blockDim.x + threadIdx.x;
    int a0 = q * 4;
    if (a0 >= A) return;
    int bd = g_boundary;

    float k4x, k4y, k4z, k4w;
    if (a0 + 3 < A) {
        float4 v = ((const float4*)g_keys_in)[q];
        k4x = v.x; k4y = v.y; k4z = v.z; k4w = v.w;
    } else {
        k4x = g_keys_in[a0];
        k4y = (a0 + 1 < A) ? g_keys_in[a0 + 1] : 0.f;
        k4z = (a0 + 2 < A) ? g_keys_in[a0 + 2] : 0.f;
        k4w = (a0 + 3 < A) ? g_keys_in[a0 + 3] : 0.f;
    }
    float kk[4] = {k4x, k4y, k4z, k4w};
    #pragma unroll
    for (int r = 0; r < 4; r++) {
        float k = kk[r];
        if (!(k > PSTTHD)) continue;
        unsigned bits = __float_as_uint(k);
        if ((int)rbucket(bits) <= bd) {
            int a = a0 + r;
            int p = atomicAdd(&g_scnt, 1);
            g_ckeys[p] = ((unsigned long long)bits << 18) |
                         (unsigned long long)(0x3FFFFu - (unsigned)a);
        }
    }
}

// ---------------------------------------------------------------------------
// One block of T0 threads: rank by comparison (keys unique), direct scatter.
// ---------------------------------------------------------------------------
__global__ void rank_kernel()
{
    __shared__ unsigned long long sk[T0];
    int t = threadIdx.x;
    int n = g_scnt;
    sk[t] = (t < n) ? g_ckeys[t] : 0ULL;
    __syncthreads();

    if (t < n) {
        unsigned long long mykey = sk[t];
        int r = 0;
        for (int j = 0; j < n; j++) r += (sk[j] > mykey) ? 1 : 0;
        int a = (int)(0x3FFFFu - (unsigned)(mykey & 0x3FFFFULL));
        g_cidx[r]  = a;
        g_cbox[r]  = g_boxes[a];
        g_carea[r] = g_areas[a];
    }
}

// ---------------------------------------------------------------------------
__global__ void pair_kernel()
{
    int tid = blockIdx.x * blockDim.x + threadIdx.x;
    if (tid >= T0 * W0) return;
    int i = tid / W0;
    int w = tid % W0;
    int T = g_T;

    int jbase = w * 64;
    if (jbase >= i || i >= T) {
        g_mask[i * W0 + w] = 0ULL;
        return;
    }

    float4 bi = g_cbox[i];
    float  ai = g_carea[i];

    unsigned long long word = 0ULL;
    int jend = min(jbase + 64, i);
    for (int j = jbase; j < jend; j++) {
        float4 bj = g_cbox[j];
        float  aj = g_carea[j];
        if (sup_test(bi.x, bi.y, bi.z, bi.w, ai, bj.x, bj.y, bj.z, bj.w, aj))
            word |= 1ULL << (j - jbase);
    }
    g_mask[i * W0 + w] = word;
}

// ---------------------------------------------------------------------------
// 1-warp exact greedy over the slab + fused kept-set resolve.
// ---------------------------------------------------------------------------
__device__ __forceinline__ void load_chunk(unsigned long long (&b)[16],
                                           int base, int Tlim, int lane)
{
    #pragma unroll
    for (int r = 0; r < 16; r++) {
        int i = base + r;
        b[r] = (i < Tlim && lane < W0) ? g_mask[(size_t)i * W0 + lane] : 0ULL;
    }
}

__global__ void scan0_kernel()
{
    __shared__ int spos[MAXDET];
    int lane = threadIdx.x;
    int Tlim = g_T;
    unsigned long long kept = 0ULL;
    int nk = 0;
    bool done = false;

    unsigned long long bufA[16], bufB[16];
    load_chunk(bufA, 0, Tlim, lane);

    for (int base = 0; base < Tlim && !done; base += 32) {
        load_chunk(bufB, base + 16, Tlim, lane);
        #pragma unroll
        for (int r = 0; r < 16; r++) {
            int i = base + r;
            if (i >= Tlim) { done = true; break; }
            bool hit = (bufA[r] & kept) != 0ULL;
            if (!__any_sync(0xffffffffu, hit)) {
                if (lane == (i >> 6)) kept |= 1ULL << (i & 63);
                if (lane == 0) spos[nk] = i;
                nk++;
                if (nk >= MAXDET) { done = true; break; }
            }
        }
        if (done) break;
        load_chunk(bufA, base + 32, Tlim, lane);
        #pragma unroll
        for (int r = 0; r < 16; r++) {
            int i = base + 16 + r;
            if (i >= Tlim) { done = true; break; }
            bool hit = (bufB[r] & kept) != 0ULL;
            if (!__any_sync(0xffffffffu, hit)) {
                if (lane == (i >> 6)) kept |= 1ULL << (i & 63);
                if (lane == 0) spos[nk] = i;
                nk++;
                if (nk >= MAXDET) { done = true; break; }
            }
        }
    }

    __syncwarp();
    for (int k = lane; k < nk; k += 32) {     // nk is warp-uniform
        int pos = spos[k];
        g_keep[k]  = g_cidx[pos];
        g_kbox[k]  = g_cbox[pos];
        g_karea[k] = g_carea[pos];
    }
    if (lane == 0) g_nk = nk;
}

// ---------------------------------------------------------------------------
__global__ void flagA_kernel(int A)
{
    __shared__ float4 skb[MAXDET];
    __shared__ float  ska[MAXDET];
    __shared__ int    snk;
    if (threadIdx.x == 0) snk = g_nk;
    __syncthreads();
    int nk = snk;
    if (nk >= MAXDET) return;
    for (int k = threadIdx.x; k < nk; k += blockDim.x) {
        skb[k] = g_kbox[k];
        ska[k] = g_karea[k];
    }
    __syncthreads();

    int a = blockIdx.x * blockDim.x + threadIdx.x;
    if (a >= A) return;
    float key = g_keys_in[a];
    if (!(key > PSTTHD)) return;
    unsigned bits = __float_as_uint(key);
    if ((int)rbucket(bits) <= g_boundary) return;   // slab member, already done

    float4 b = g_boxes[a];
    float ar = g_areas[a];
    for (int k = 0; k < nk; k++) {
        if (sup_test(b.x, b.y, b.z, b.w, ar,
                     skb[k].x, skb[k].y, skb[k].z, skb[k].w, ska[k]))
            return;
    }
    int p = atomicAdd(&g_nsurv, 1);
    if (p < CAP)
        g_skey[p] = ((unsigned long long)bits << 18) |
                    (unsigned long long)(0x3FFFFu - (unsigned)a);
}

// ---------------------------------------------------------------------------
__global__ void tailC_kernel()
{
    __shared__ unsigned long long sb[1024];
    __shared__ float4 swin;
    __shared__ float  swar;
    int t = threadIdx.x;
    int nk = g_nk;
    int ns = min(g_nsurv, CAP);

    if (nk < MAXDET && ns > 0) {
        while (true) {
            unsigned long long best = 0ULL;
            for (int i = t; i < ns; i += 1024) {
                unsigned long long v = g_skey[i];
                if (v > best) best = v;
            }
            sb[t] = best;
            __syncthreads();
            for (int off = 512; off; off >>= 1) {
                if (t < off && sb[t + off] > sb[t]) sb[t] = sb[t + off];
                __syncthreads();
            }
            if (sb[0] == 0ULL) break;

            if (t == 0) {
                int a = (int)(0x3FFFFu - (unsigned)(sb[0] & 0x3FFFFULL));
                float4 b = g_boxes[a];
                float ar = g_areas[a];
                g_keep[nk]  = a;
                g_kbox[nk]  = b;
                g_karea[nk] = ar;
                swin = b; swar = ar;
            }
            __syncthreads();
            float4 wb = swin;
            float war = swar;
            for (int i = t; i < ns; i += 1024) {
                unsigned long long v = g_skey[i];
                if (v != 0ULL) {
                    int a = (int)(0x3FFFFu - (unsigned)(v & 0x3FFFFULL));
                    float4 b = g_boxes[a];
                    if (sup_test(b.x, b.y, b.z, b.w, g_areas[a],
                                 wb.x, wb.y, wb.z, wb.w, war))
                        g_skey[i] = 0ULL;
                }
            }
            nk++;
            if (nk >= MAXDET) break;
            __syncthreads();
        }
    }
    if (t == 0) g_nk = nk;
}

// ---------------------------------------------------------------------------
__global__ void final_kernel(const float* __restrict__ cls, int C,
                             float* __restrict__ out)
{
    int warp = (blockIdx.x * blockDim.x + threadIdx.x) >> 5;
    int lane = threadIdx.x & 31;
    if (warp >= MAXDET) return;

    int nk = g_nk;
    bool valid = warp < nk;
    float score = 0.f, clsid = -1.f;
    float bx0 = 0.f, bx1 = 0.f, bx2 = 0.f, bx3 = 0.f;

    if (valid) {
        int idx = g_keep[warp];
        const float* row = cls + (size_t)idx * C;
        float best = -FLT_MAX;
        int bi = 0x7fffffff;
        for (int c = lane; c < C; c += 32) {
            float vv = row[c];
            if (vv > best) { best = vv; bi = c; }
        }
        #pragma unroll
        for (int off = 16; off; off >>= 1) {
            float ov = __shfl_down_sync(0xffffffffu, best, off);
            int   oi = __shfl_down_sync(0xffffffffu, bi,   off);
            if (ov > best || (ov == best && oi < bi)) { best = ov; bi = oi; }
        }
        best = __shfl_sync(0xffffffffu, best, 0);
        bi   = __shfl_sync(0xffffffffu, bi,   0);
        score = best;
        clsid = (float)bi;
        float4 b = g_kbox[warp];
        bx0 = b.x; bx1 = b.y; bx2 = b.z; bx3 = b.w;
    }
    if (lane == 0) {
        out[warp]                      = score;
        out[MAXDET + warp]             = clsid;
        out[2 * MAXDET + 4 * warp + 0] = bx0;
        out[2 * MAXDET + 4 * warp + 1] = bx1;
        out[2 * MAXDET + 4 * warp + 2] = bx2;
        out[2 * MAXDET + 4 * warp + 3] = bx3;
        out[6 * MAXDET + warp]         = valid ? 1.0f : 0.0f;
    }
}

// ---------------------------------------------------------------------------
extern "C" void kernel_launch(void* const* d_in, const int* in_sizes, int n_in,
                              void* d_out, int out_size)
{
    const float* cls = (const float*)d_in[0];
    const float* reg = (const float*)d_in[1];
    const float* anc = (const float*)d_in[2];
    const int*   ph  = (n_in > 3) ? (const int*)d_in[3] : nullptr;
    const int*   pw  = (n_in > 4) ? (const int*)d_in[4] : nullptr;

    int A = in_sizes[2] / 4;
    if (A > MAXA) A = MAXA;
    int C = in_sizes[0] / A;

    zero_kernel<<<NBKT / 1024, 1024>>>();
    prep2_kernel<<<(A + 31) / 32, 256>>>(cls, reg, anc, ph, pw, A, C);
    scanB_kernel<<<1, 1024>>>();
    compact_kernel<<<(A / 4 + 255) / 256, 256>>>(A);
    rank_kernel<<<1, T0>>>();
    pair_kernel<<<T0 * W0 / 256, 256>>>();
    scan0_kernel<<<1, 32>>>();
    flagA_kernel<<<(A + 255) / 256, 256>>>(A);
    tailC_kernel<<<1, 1024>>>();
    final_kernel<<<(MAXDET * 32 + 127) / 128, 128>>>(cls, C, (float*)d_out);
}